// round 1
// baseline (speedup 1.0000x reference)
#include <cuda_runtime.h>
#include <cstdint>

// Problem: out[i] = one_hot(argmax_j( sum_k x[i,k]*W[k,j] + b[j] ), 64)
// x: [B,64] f32, W: [64,64] f32 (k-major), b: [64] f32, out: [B,64] f32.
//
// Design (FFMA-pipe bound):
//  - W+b resident in shared, k-major -> every lane reads the SAME address
//    per step => LDS broadcast (conflict-free, 1 wavefront).
//  - Packed fp32 math via fma.rn.f32x2 (sm_103a): 2 MACs per FMA-pipe slot.
//  - x tile and one-hot output staged through shared so all global traffic
//    is fully coalesced (thread-per-row direct I/O would 8x the L1 wavefronts).

#define DIMS 64
#define TPB 256
#define ROWS_PER_BLOCK 256
#define XS_PAD 66   // even (float2-aligned rows), (2t+k)%32 -> <=2-way conflicts

// dynamic smem layout (floats): Ws[64*64] | bs[64] | xs[256*66]
#define SMEM_FLOATS (DIMS * DIMS + DIMS + ROWS_PER_BLOCK * XS_PAD)
#define SMEM_BYTES (SMEM_FLOATS * 4)

__device__ __forceinline__ unsigned long long fma2(unsigned long long a,
                                                   unsigned long long b,
                                                   unsigned long long c) {
    unsigned long long d;
    asm("fma.rn.f32x2 %0, %1, %2, %3;" : "=l"(d) : "l"(a), "l"(b), "l"(c));
    return d;
}

__global__ void __launch_bounds__(TPB)
onehot_argmax_kernel(const float* __restrict__ x,
                     const float* __restrict__ W,
                     const float* __restrict__ b,
                     float* __restrict__ out) {
    extern __shared__ float smem[];
    float* Ws = smem;                    // 64*64, k-major: Ws[k*64 + j]
    float* bs = Ws + DIMS * DIMS;        // 64
    float* xs = bs + DIMS;               // 256 rows * 66 pad

    const int tid = threadIdx.x;
    const long long base = (long long)blockIdx.x * ROWS_PER_BLOCK;

    // ---- load W (1024 float4, coalesced) + b into shared ----
    {
        const float4* W4 = (const float4*)W;
        float4* Ws4 = (float4*)Ws;
#pragma unroll
        for (int f = 0; f < 4; f++) Ws4[tid + f * TPB] = W4[tid + f * TPB];
        if (tid < DIMS / 4) ((float4*)bs)[tid] = ((const float4*)b)[tid];
    }

    // ---- stage x tile: 256 rows * 64 f32, coalesced float4 loads ----
    {
        const float4* xg = (const float4*)x + base * (DIMS / 4);
#pragma unroll
        for (int it = 0; it < 16; it++) {
            int f = tid + it * TPB;          // 0..4095
            float4 v = xg[f];
            int row = f >> 4, q = f & 15;
            float2* p = (float2*)(xs + row * XS_PAD + q * 4);
            p[0] = make_float2(v.x, v.y);
            p[1] = make_float2(v.z, v.w);
        }
    }
    __syncthreads();

    // ---- per-thread matvec: acc[j] = b[j] + sum_k x[k]*W[k,j], packed x2 ----
    unsigned long long acc[32];
#pragma unroll
    for (int jj = 0; jj < 32; jj++)
        acc[jj] = *(const unsigned long long*)(bs + 2 * jj);  // (b[2jj], b[2jj+1])

    const float* xrow = xs + tid * XS_PAD;
#pragma unroll 4
    for (int k = 0; k < DIMS; k++) {
        float xk = xrow[k];
        unsigned long long xk2;
        asm("mov.b64 %0, {%1, %1};" : "=l"(xk2) : "f"(xk));
        const ulonglong2* wr = (const ulonglong2*)(Ws + (k << 6));  // broadcast
#pragma unroll
        for (int jq = 0; jq < 16; jq++) {
            ulonglong2 w = wr[jq];
            acc[2 * jq]     = fma2(xk2, w.x, acc[2 * jq]);
            acc[2 * jq + 1] = fma2(xk2, w.y, acc[2 * jq + 1]);
        }
    }

    // ---- argmax (ascending j, strict > => first-max, matches jnp.argmax) ----
    float best = -__int_as_float(0x7f800000);  // -inf
    int bidx = 0;
#pragma unroll
    for (int jj = 0; jj < 32; jj++) {
        float lo, hi;
        asm("mov.b64 {%0, %1}, %2;" : "=f"(lo), "=f"(hi) : "l"(acc[jj]));
        if (lo > best) { best = lo; bidx = 2 * jj; }
        if (hi > best) { best = hi; bidx = 2 * jj + 1; }
    }

    // ---- write one-hot row into xs (own row only; no sync needed yet) ----
    {
        float2* orow = (float2*)(xs + tid * XS_PAD);
        float2 z = make_float2(0.f, 0.f);
#pragma unroll
        for (int h = 0; h < 32; h++) orow[h] = z;
        xs[tid * XS_PAD + bidx] = 1.0f;
    }
    __syncthreads();

    // ---- coalesced store: 256 rows * 32 float2 ----
    {
        float2* og = (float2*)out + base * (DIMS / 2);
#pragma unroll
        for (int it = 0; it < 32; it++) {
            int f = tid + it * TPB;          // 0..8191
            int row = f >> 5, q = f & 31;
            og[f] = *(const float2*)(xs + row * XS_PAD + 2 * q);
        }
    }
}

extern "C" void kernel_launch(void* const* d_in, const int* in_sizes, int n_in,
                              void* d_out, int out_size) {
    const float* x = (const float*)d_in[0];
    const float* W = (const float*)d_in[1];
    const float* b = (const float*)d_in[2];
    float* out = (float*)d_out;

    const long long rows = (long long)in_sizes[0] / DIMS;  // 2097152
    const int blocks = (int)(rows / ROWS_PER_BLOCK);       // 8192

    cudaFuncSetAttribute(onehot_argmax_kernel,
                         cudaFuncAttributeMaxDynamicSharedMemorySize, SMEM_BYTES);
    onehot_argmax_kernel<<<blocks, TPB, SMEM_BYTES>>>(x, W, b, out);
}

// round 2
// speedup vs baseline: 1.4183x; 1.4183x over previous
#include <cuda_runtime.h>
#include <cstdint>

// out[i] = one_hot(argmax_j( b[j] + sum_k x[i,k]*W[k,j] ), 64)
//
// Decomposition: 256 threads/block, 256 rows/block.
//   group g = t>>2 owns rows 4g..4g+3; a = t&3 owns columns {16c + 4a + e}.
//   => W smem reads amortized over 4 rows; acc = 32 f32x2 regs (64 regs).
// Numerics: per column, single ascending-k fp32 FMA chain init'd with b —
//   bit-identical to the round-1 passing kernel (rel_err = 1/1024, 1 row flip).
// Shared layout avoids bank conflicts:
//   - W[k][j] plain; thread reads j = 16c+4a.. -> 4 distinct bank-quads.
//   - x tile swizzled: float4 (row, kq) at row*64 + ((4kq) ^ (row & 0x1C))
//     -> mainloop LDS.128 across 8 row-groups hits 8 distinct bank-quads.
// Output computed from labels (no zero-fill stores).

#define DIMS 64
#define TPB 256
#define ROWS 256

// smem floats: Ws[4096] | bs[64] | xs[16384] | ls[256 ints]
#define SMEM_FLOATS (4096 + 64 + 16384 + 256)
#define SMEM_BYTES (SMEM_FLOATS * 4)

__device__ __forceinline__ unsigned long long fma2(unsigned long long a,
                                                   unsigned long long b,
                                                   unsigned long long c) {
    unsigned long long d;
    asm("fma.rn.f32x2 %0, %1, %2, %3;" : "=l"(d) : "l"(a), "l"(b), "l"(c));
    return d;
}
__device__ __forceinline__ unsigned long long dup2(float x) {
    unsigned long long d;
    asm("mov.b64 %0, {%1, %1};" : "=l"(d) : "f"(x));
    return d;
}
__device__ __forceinline__ void unpack2(unsigned long long v, float& lo, float& hi) {
    asm("mov.b64 {%0, %1}, %2;" : "=f"(lo), "=f"(hi) : "l"(v));
}

__global__ void __launch_bounds__(TPB, 2)
onehot_argmax_kernel(const float* __restrict__ x,
                     const float* __restrict__ W,
                     const float* __restrict__ b,
                     float* __restrict__ out) {
    extern __shared__ float smem[];
    float* Ws = smem;            // [64][64], k-major
    float* bs = Ws + 4096;       // [64]
    float* xs = bs + 64;         // swizzled x tile, 256*64 floats
    int*   ls = (int*)(xs + 16384);  // labels [256]

    const int t = threadIdx.x;
    const int g = t >> 2;        // row group (0..63), rows 4g..4g+3
    const int a = t & 3;         // column quarter selector
    const long long gbase4 = (long long)blockIdx.x * (ROWS * (DIMS / 4));

    // ---- stage W + b (coalesced float4) ----
    {
        const float4* W4 = (const float4*)W;
        float4* Ws4 = (float4*)Ws;
#pragma unroll
        for (int i = 0; i < 4; i++) Ws4[t + i * TPB] = W4[t + i * TPB];
        if (t < 16) ((float4*)bs)[t] = ((const float4*)b)[t];
    }

    // ---- stage x tile, swizzled ----
    {
        const float4* xg = (const float4*)x + gbase4;
#pragma unroll
        for (int it = 0; it < 16; it++) {
            int f = t + it * TPB;        // 0..4095
            int row = f >> 4, q = f & 15;
            float4 v = xg[f];
            int off = row * 64 + ((4 * q) ^ (row & 0x1C));
            *(float4*)(xs + off) = v;
        }
    }
    __syncthreads();

    // ---- init acc with b (columns j = 16c + 4a + {0..3}) ----
    unsigned long long acc[4][8];
#pragma unroll
    for (int c = 0; c < 4; c++) {
        ulonglong2 bv = *(const ulonglong2*)(bs + 16 * c + 4 * a);
#pragma unroll
        for (int i = 0; i < 4; i++) { acc[i][2 * c] = bv.x; acc[i][2 * c + 1] = bv.y; }
    }

    int rb[4], sw[4];
#pragma unroll
    for (int i = 0; i < 4; i++) {
        int row = 4 * g + i;
        rb[i] = row * 64;
        sw[i] = row & 0x1C;
    }

    // ---- mainloop: 16 k-quads ----
    for (int kq = 0; kq < 16; kq++) {
        float4 xr[4];
#pragma unroll
        for (int i = 0; i < 4; i++)
            xr[i] = *(const float4*)(xs + rb[i] + ((4 * kq) ^ sw[i]));
#pragma unroll
        for (int dk = 0; dk < 4; dk++) {
            const int k = 4 * kq + dk;
            ulonglong2 w[4];
#pragma unroll
            for (int c = 0; c < 4; c++)
                w[c] = *(const ulonglong2*)(Ws + k * 64 + 16 * c + 4 * a);
#pragma unroll
            for (int i = 0; i < 4; i++) {
                float xk = (dk == 0) ? xr[i].x : (dk == 1) ? xr[i].y
                         : (dk == 2) ? xr[i].z : xr[i].w;
                unsigned long long x2 = dup2(xk);
#pragma unroll
                for (int c = 0; c < 4; c++) {
                    acc[i][2 * c]     = fma2(x2, w[c].x, acc[i][2 * c]);
                    acc[i][2 * c + 1] = fma2(x2, w[c].y, acc[i][2 * c + 1]);
                }
            }
        }
    }

    // ---- per-thread argmax over its 16 columns (ascending j, strict >) ----
    float bv[4];
    int bj[4];
#pragma unroll
    for (int i = 0; i < 4; i++) { bv[i] = __int_as_float(0xff800000); bj[i] = 0; }
#pragma unroll
    for (int c = 0; c < 4; c++) {
#pragma unroll
        for (int p = 0; p < 2; p++) {
            int j0 = 16 * c + 4 * a + 2 * p;
#pragma unroll
            for (int i = 0; i < 4; i++) {
                float lo, hi;
                unpack2(acc[i][2 * c + p], lo, hi);
                if (lo > bv[i]) { bv[i] = lo; bj[i] = j0; }
                if (hi > bv[i]) { bv[i] = hi; bj[i] = j0 + 1; }
            }
        }
    }

    // ---- reduce across the 4 threads of the group (first-max tie-break) ----
#pragma unroll
    for (int off = 1; off <= 2; off <<= 1) {
#pragma unroll
        for (int i = 0; i < 4; i++) {
            float pv = __shfl_xor_sync(0xffffffffu, bv[i], off);
            int   pj = __shfl_xor_sync(0xffffffffu, bj[i], off);
            if (pv > bv[i] || (pv == bv[i] && pj < bj[i])) { bv[i] = pv; bj[i] = pj; }
        }
    }
    if (a == 0) {
#pragma unroll
        for (int i = 0; i < 4; i++) ls[4 * g + i] = bj[i];
    }
    __syncthreads();

    // ---- computed one-hot store (coalesced float4) ----
    {
        float4* og = (float4*)out + gbase4;
#pragma unroll
        for (int it = 0; it < 16; it++) {
            int f = t + it * TPB;
            int row = f >> 4, q = f & 15;
            int lab = ls[row];
            float4 v;
            v.x = (4 * q + 0 == lab) ? 1.0f : 0.0f;
            v.y = (4 * q + 1 == lab) ? 1.0f : 0.0f;
            v.z = (4 * q + 2 == lab) ? 1.0f : 0.0f;
            v.w = (4 * q + 3 == lab) ? 1.0f : 0.0f;
            og[f] = v;
        }
    }
}

extern "C" void kernel_launch(void* const* d_in, const int* in_sizes, int n_in,
                              void* d_out, int out_size) {
    const float* x = (const float*)d_in[0];
    const float* W = (const float*)d_in[1];
    const float* b = (const float*)d_in[2];
    float* out = (float*)d_out;

    const long long rows = (long long)in_sizes[0] / DIMS;   // 2097152
    const int blocks = (int)(rows / ROWS);                   // 8192

    cudaFuncSetAttribute(onehot_argmax_kernel,
                         cudaFuncAttributeMaxDynamicSharedMemorySize, SMEM_BYTES);
    onehot_argmax_kernel<<<blocks, TPB, SMEM_BYTES>>>(x, W, b, out);
}

// round 3
// speedup vs baseline: 1.5110x; 1.0653x over previous
#include <cuda_runtime.h>
#include <cstdint>

// out[i] = one_hot(argmax_j( b[j] + sum_k x[i,k]*W[k,j] ), 64)
//
// R3 scheme: 256 threads/block, 256 rows/block.
//   g = t>>3 owns rows 8g..8g+7 ; a = t&7 owns cols {4a..4a+3} U {32+4a..32+4a+3}
//   => W smem loads amortized over 8 rows: 2 LDS.128/k (was 4); x: 2/k.
//   acc = 8 rows x 8 cols packed f32x2 = 32 u64 = 64 regs.
// Numerics: per column, b-init + ascending-k fp32 FMA chain (bit-identical to
//   the passing round-1/2 kernels; rel_err = 1 flipped row, zero margin).
// Staging via cp.async (no LDG->reg->STS round trip).

#define DIMS 64
#define TPB 256
#define ROWS 256

// smem floats: Ws[4096] | bs[64] | xs[16384] | ls[256 ints]
#define SMEM_FLOATS (4096 + 64 + 16384 + 256)
#define SMEM_BYTES (SMEM_FLOATS * 4)

__device__ __forceinline__ unsigned long long fma2(unsigned long long a,
                                                   unsigned long long b,
                                                   unsigned long long c) {
    unsigned long long d;
    asm("fma.rn.f32x2 %0, %1, %2, %3;" : "=l"(d) : "l"(a), "l"(b), "l"(c));
    return d;
}
__device__ __forceinline__ unsigned long long dup2(float x) {
    unsigned long long d;
    asm("mov.b64 %0, {%1, %1};" : "=l"(d) : "f"(x));
    return d;
}
__device__ __forceinline__ void unpack2(unsigned long long v, float& lo, float& hi) {
    asm("mov.b64 {%0, %1}, %2;" : "=f"(lo), "=f"(hi) : "l"(v));
}
__device__ __forceinline__ void cp16(uint32_t dst, const void* src) {
    asm volatile("cp.async.cg.shared.global [%0], [%1], 16;" :: "r"(dst), "l"(src));
}

__global__ void __launch_bounds__(TPB, 2)
onehot_argmax_kernel(const float* __restrict__ x,
                     const float* __restrict__ W,
                     const float* __restrict__ b,
                     float* __restrict__ out) {
    extern __shared__ float smem[];
    float* Ws = smem;                 // [64][64] k-major
    float* bs = Ws + 4096;            // [64]
    float* xs = bs + 64;              // swizzled x tile, 256*64 floats
    int*   ls = (int*)(xs + 16384);   // labels [256]

    const int t = threadIdx.x;
    const int g = t >> 3;             // row group 0..31, rows 8g..8g+7
    const int a = t & 7;              // column selector
    const long long gbase4 = (long long)blockIdx.x * (ROWS * (DIMS / 4));

    const uint32_t s_ws = (uint32_t)__cvta_generic_to_shared(Ws);
    const uint32_t s_bs = (uint32_t)__cvta_generic_to_shared(bs);
    const uint32_t s_xs = (uint32_t)__cvta_generic_to_shared(xs);

    // ---- stage W (1024 float4), b (16 float4), x tile (4096 float4) ----
    {
        const float4* W4 = (const float4*)W;
#pragma unroll
        for (int i = 0; i < 4; i++)
            cp16(s_ws + (t + i * TPB) * 16, W4 + t + i * TPB);
        if (t < 16) cp16(s_bs + t * 16, ((const float4*)b) + t);

        const float4* xg = (const float4*)x + gbase4;
#pragma unroll
        for (int it = 0; it < 16; it++) {
            int f = t + it * TPB;             // 0..4095
            int row = f >> 4, q = f & 15;
            int off = row * 64 + ((4 * q) ^ (row & 0x1C));
            cp16(s_xs + off * 4, xg + f);
        }
        asm volatile("cp.async.commit_group;" ::: "memory");
        asm volatile("cp.async.wait_group 0;" ::: "memory");
    }
    __syncthreads();

    // ---- init acc with b: cols {4a..4a+3} and {32+4a..32+4a+3} ----
    unsigned long long acc[8][4];
    {
        ulonglong2 b0 = *(const ulonglong2*)(bs + 4 * a);
        ulonglong2 b1 = *(const ulonglong2*)(bs + 32 + 4 * a);
#pragma unroll
        for (int i = 0; i < 8; i++) {
            acc[i][0] = b0.x; acc[i][1] = b0.y;
            acc[i][2] = b1.x; acc[i][3] = b1.y;
        }
    }

    // row addressing: row_i = 8g+i; base = 8g*64; swizzle = (g&3)*8 + (i&4)
    const float* xbase = xs + (g << 9);       // 8g * 64
    const int swb = (g & 3) << 3;

    // ---- mainloop: 16 k-quads, 64 k total ----
#pragma unroll 2
    for (int kq = 0; kq < 16; kq++) {
        const int e0 = (4 * kq) ^ swb;        // for i & 4 == 0
        const int e4 = (4 * kq) ^ (swb + 4);  // for i & 4 == 4
        float4 xr[8];
#pragma unroll
        for (int i = 0; i < 8; i++)
            xr[i] = *(const float4*)(xbase + (i << 6) + ((i & 4) ? e4 : e0));
#pragma unroll
        for (int dk = 0; dk < 4; dk++) {
            const int k = 4 * kq + dk;
            ulonglong2 w0 = *(const ulonglong2*)(Ws + (k << 6) + 4 * a);
            ulonglong2 w1 = *(const ulonglong2*)(Ws + (k << 6) + 32 + 4 * a);
#pragma unroll
            for (int i = 0; i < 8; i++) {
                float xk = (dk == 0) ? xr[i].x : (dk == 1) ? xr[i].y
                         : (dk == 2) ? xr[i].z : xr[i].w;
                unsigned long long x2 = dup2(xk);
                acc[i][0] = fma2(x2, w0.x, acc[i][0]);
                acc[i][1] = fma2(x2, w0.y, acc[i][1]);
                acc[i][2] = fma2(x2, w1.x, acc[i][2]);
                acc[i][3] = fma2(x2, w1.y, acc[i][3]);
            }
        }
    }

    // ---- per-thread argmax over its 8 cols (ascending j, strict >) ----
    float bv[8];
    int bj[8];
#pragma unroll
    for (int i = 0; i < 8; i++) { bv[i] = __int_as_float(0xff800000); bj[i] = 0; }
#pragma unroll
    for (int c = 0; c < 4; c++) {
        const int j0 = (c < 2) ? (4 * a + 2 * c) : (32 + 4 * a + 2 * (c - 2));
#pragma unroll
        for (int i = 0; i < 8; i++) {
            float lo, hi;
            unpack2(acc[i][c], lo, hi);
            if (lo > bv[i]) { bv[i] = lo; bj[i] = j0; }
            if (hi > bv[i]) { bv[i] = hi; bj[i] = j0 + 1; }
        }
    }

    // ---- reduce across the 8 column-threads (first-max tie-break) ----
#pragma unroll
    for (int off = 1; off <= 4; off <<= 1) {
#pragma unroll
        for (int i = 0; i < 8; i++) {
            float pv = __shfl_xor_sync(0xffffffffu, bv[i], off);
            int   pj = __shfl_xor_sync(0xffffffffu, bj[i], off);
            if (pv > bv[i] || (pv == bv[i] && pj < bj[i])) { bv[i] = pv; bj[i] = pj; }
        }
    }
    if (a == 0) {
#pragma unroll
        for (int i = 0; i < 8; i++) ls[8 * g + i] = bj[i];
    }
    __syncthreads();

    // ---- computed one-hot store (coalesced float4) ----
    {
        float4* og = (float4*)out + gbase4;
#pragma unroll
        for (int it = 0; it < 16; it++) {
            int f = t + it * TPB;
            int row = f >> 4, q = f & 15;
            int lab = ls[row];
            float4 v;
            v.x = (4 * q + 0 == lab) ? 1.0f : 0.0f;
            v.y = (4 * q + 1 == lab) ? 1.0f : 0.0f;
            v.z = (4 * q + 2 == lab) ? 1.0f : 0.0f;
            v.w = (4 * q + 3 == lab) ? 1.0f : 0.0f;
            og[f] = v;
        }
    }
}

extern "C" void kernel_launch(void* const* d_in, const int* in_sizes, int n_in,
                              void* d_out, int out_size) {
    const float* x = (const float*)d_in[0];
    const float* W = (const float*)d_in[1];
    const float* b = (const float*)d_in[2];
    float* out = (float*)d_out;

    const long long rows = (long long)in_sizes[0] / DIMS;   // 2097152
    const int blocks = (int)(rows / ROWS);                   // 8192

    cudaFuncSetAttribute(onehot_argmax_kernel,
                         cudaFuncAttributeMaxDynamicSharedMemorySize, SMEM_BYTES);
    onehot_argmax_kernel<<<blocks, TPB, SMEM_BYTES>>>(x, W, b, out);
}